// round 7
// baseline (speedup 1.0000x reference)
#include <cuda_runtime.h>
#include <cuda_fp16.h>

#define BB 16
#define CC 32
#define TPB 128
#define MAXBLK 2048

// Scratch (no device allocations). g_bar self-resets -> graph-replay safe.
__device__ double g_partials[MAXBLK];
__device__ unsigned int g_bar = 0;

__device__ __forceinline__ float fast_ex2(float x) {
    float r; asm("ex2.approx.ftz.f32 %0, %1;" : "=f"(r) : "f"(x)); return r;
}
__device__ __forceinline__ float fast_lg2(float x) {
    float r; asm("lg2.approx.ftz.f32 %0, %1;" : "=f"(r) : "f"(x)); return r;
}

// FMA-pipe 2^d for d >= 0 (d < ~120). Magic split d = k + r, r in [-0.5, 0.5],
// deg-4 Taylor for 2^r, exponent inserted via bit add. MAGIC = 1.5*2^23 has
// zero low-9 bits, so (bits(t) << 23) == k << 23 exactly (k < 512).
__device__ __forceinline__ float poly_ex2(float d) {
    const float MAGIC = 12582912.0f;          // 0x4B400000
    const float t = d + MAGIC;                // mantissa low bits = round(d)
    const float r = d - (t - MAGIC);          // r in [-0.5, 0.5]
    float p = 0.00961812910762848f;           // (ln2)^4/24
    p = fmaf(p, r, 0.0555041086648216f);      // (ln2)^3/6
    p = fmaf(p, r, 0.240226506959101f);       // (ln2)^2/2
    p = fmaf(p, r, 0.693147180559945f);       // ln2
    p = fmaf(p, r, 1.0f);
    return __int_as_float(__float_as_int(p) + (__float_as_int(t) << 23));
}

// Class-split: each n handled by a lane pair (lane ^ 16); half owns 16 classes.
// b-loop double-buffered; f-phase exp on the FMA pipe (poly), sum-phase exp on MUFU.
template <int NC>
__global__ void __launch_bounds__(TPB, 8) fpce_fused(const float* __restrict__ pred,
                                                     const int* __restrict__ tru,
                                                     int Nrt,
                                                     float* __restrict__ out) {
    const int N = (NC > 0) ? NC : Nrt;
    const float LOG2E = 1.4426950408889634f;

    const int tid  = threadIdx.x;
    const int lane = tid & 31;
    const int half = lane >> 4;
    const int warp = tid >> 5;
    const int NPB  = TPB / 2;             // 64 n per block

    float thread_total = 0.0f;

    for (int n0 = blockIdx.x * NPB; n0 < N; n0 += gridDim.x * NPB) {
        int n = n0 + warp * 16 + (lane & 15);
        const bool valid = (n < N);
        if (!valid) n = N - 1;            // clamp keeps pair lanes convergent

        // ---- Counts for MY 16 classes: 8-bit fields in 2 u64 regs.
        unsigned long long p0 = 0ull, p1 = 0ull;
#pragma unroll
        for (int b = 0; b < BB; b++) {
            const int t  = tru[b * N + n];
            const int lt = t - (half << 4);
            const unsigned long long inc = 1ull << ((lt & 7) << 3);
            const bool mine = (lt >= 0) && (lt < 16);
            p0 += (mine && lt < 8) ? inc : 0ull;
            p1 += (mine && lt >= 8) ? inc : 0ull;
        }
        __half2 cnth[8];
#pragma unroll
        for (int i = 0; i < 2; i++) {
            const unsigned long long p = i ? p1 : p0;
#pragma unroll
            for (int j = 0; j < 4; j++) {
                const float lo = (float)((unsigned)(p >> (16 * j)) & 0xFFu);
                const float hi = (float)((unsigned)(p >> (16 * j + 8)) & 0xFFu);
                cnth[i * 4 + j] = __floats2half2_rn(lo, hi);
            }
        }

        const float* rowbase = pred + ((size_t)(half * 16)) * (size_t)N + (size_t)n;
        const size_t bstride = (size_t)CC * (size_t)N;

        auto compute = [&](float* y) -> float {
            // Phase 1 (MUFU): s = sum 2^y over my 16 classes, 4 parallel chains.
            float s0 = 0.f, s1 = 0.f, s2 = 0.f, s3 = 0.f;
#pragma unroll
            for (int j = 0; j < 16; j++) {
                y[j] *= LOG2E;
                const float e = fast_ex2(y[j]);
                if ((j & 3) == 0) s0 += e;
                else if ((j & 3) == 1) s1 += e;
                else if ((j & 3) == 2) s2 += e;
                else s3 += e;
            }
            const float sh = (s0 + s1) + (s2 + s3);
            const float s  = sh + __shfl_xor_sync(0xffffffffu, sh, 16);
            const float L2 = fast_lg2(s);

            // Phase 2 (FMA pipe): f = d * 2^d via poly, weighted by counts.
            float a0 = 0.f, a1 = 0.f, a2 = 0.f, a3 = 0.f;
#pragma unroll
            for (int j = 0; j < 16; j++) {
                const float d  = L2 - y[j];
                const float e  = poly_ex2(d);
                const float cf = (j & 1) ? __high2float(cnth[j >> 1])
                                         : __low2float(cnth[j >> 1]);
                const float t  = cf * d;
                if ((j & 3) == 0) a0 = fmaf(t, e, a0);
                else if ((j & 3) == 1) a1 = fmaf(t, e, a1);
                else if ((j & 3) == 2) a2 = fmaf(t, e, a2);
                else a3 = fmaf(t, e, a3);
            }
            return (a0 + a1) + (a2 + a3);
        };

        float ya[16], yb[16];
        float row_sum = 0.0f;

#pragma unroll
        for (int j = 0; j < 16; j++) ya[j] = rowbase[(size_t)j * (size_t)N];

#pragma unroll 1
        for (int b = 0; b < BB; b += 2) {
            const float* r1 = rowbase + (size_t)(b + 1) * bstride;
#pragma unroll
            for (int j = 0; j < 16; j++) yb[j] = r1[(size_t)j * (size_t)N];   // prefetch b+1
            row_sum += compute(ya);

            if (b + 2 < BB) {
                const float* r2 = rowbase + (size_t)(b + 2) * bstride;
#pragma unroll
                for (int j = 0; j < 16; j++) ya[j] = r2[(size_t)j * (size_t)N]; // prefetch b+2
            }
            row_sum += compute(yb);
        }

        thread_total += valid ? row_sum : 0.0f;
    }
    thread_total *= 0.6931471805599453f;  // ln2 once

    // ---- Block reduction (double).
    double v = (double)thread_total;
#pragma unroll
    for (int off = 16; off > 0; off >>= 1)
        v += __shfl_down_sync(0xffffffffu, v, off);

    __shared__ double wsum[TPB / 32];
    const int wid = threadIdx.x >> 5;
    if ((threadIdx.x & 31) == 0) wsum[wid] = v;
    __syncthreads();

    __shared__ int isLast;
    if (threadIdx.x == 0) {
        double bsum = 0.0;
#pragma unroll
        for (int w = 0; w < TPB / 32; w++) bsum += wsum[w];
        g_partials[blockIdx.x] = bsum;
        __threadfence();
        const unsigned done = atomicAdd(&g_bar, 1u);
        isLast = (done == gridDim.x - 1) ? 1 : 0;
    }
    __syncthreads();

    if (isLast) {
        double t = 0.0;
        for (int i = threadIdx.x; i < (int)gridDim.x; i += TPB) t += g_partials[i];
#pragma unroll
        for (int off = 16; off > 0; off >>= 1)
            t += __shfl_down_sync(0xffffffffu, t, off);
        if ((threadIdx.x & 31) == 0) wsum[wid] = t;
        __syncthreads();
        if (threadIdx.x == 0) {
            double total = 0.0;
#pragma unroll
            for (int w = 0; w < TPB / 32; w++) total += wsum[w];
            out[0] = (float)(total / (double)N);
            atomicExch(&g_bar, 0u);   // reset for next graph replay
        }
    }
}

extern "C" void kernel_launch(void* const* d_in, const int* in_sizes, int n_in,
                              void* d_out, int out_size) {
    const float* pred = (const float*)d_in[0];
    const int*   tru  = (const int*)d_in[1];
    float*       out  = (float*)d_out;

    const int N = in_sizes[1] / BB;  // true is (B, N)

    const int npb = TPB / 2;
    int blocks = (N + npb - 1) / npb;
    if (blocks > MAXBLK) blocks = MAXBLK;

    if (N == 131072) {
        fpce_fused<131072><<<blocks, TPB>>>(pred, tru, N, out);
    } else {
        fpce_fused<0><<<blocks, TPB>>>(pred, tru, N, out);
    }
}